// round 1
// baseline (speedup 1.0000x reference)
#include <cuda_runtime.h>
#include <cstdint>
#include <cstddef>

// ---------------------------------------------------------------------------
// Problem constants
// ---------------------------------------------------------------------------
#define NF 100000
#define NE 200000
#define HID 128
#define RAW 512
#define NEDGE 1000000

// ---------------------------------------------------------------------------
// Scratch (device globals -- no allocation allowed)
// ---------------------------------------------------------------------------
__device__ float g_x_fr[(size_t)NF * HID];
__device__ float g_x_fe[(size_t)NE * HID];
__device__ float g_h_fr[(size_t)NF * HID];
__device__ float g_h_fe[(size_t)NE * HID];
__device__ float g_aggFF[(size_t)NF * HID];
__device__ float g_aggEF[(size_t)NF * HID];
__device__ float g_aggFE[(size_t)NE * HID];
__device__ float g_aggEE[(size_t)NE * HID];
// degree / norm buffer: [ns_ff NF][nd_ff NF][ns_frfe NF][nd_fefr NF]
//                       [nd_frfe NE][ns_fefr NE][ns_ee NE][nd_ee NE]
__device__ float g_deg[(size_t)4 * NF + (size_t)4 * NE];

// ---------------------------------------------------------------------------
// Utility kernels
// ---------------------------------------------------------------------------
__global__ void zero_kernel(float* __restrict__ p, size_t n4) {
    size_t i = (size_t)blockIdx.x * blockDim.x + threadIdx.x;
    if (i < n4) ((float4*)p)[i] = make_float4(0.f, 0.f, 0.f, 0.f);
}

__global__ void deg_kernel(const int* __restrict__ src, const int* __restrict__ dst,
                           float* __restrict__ dout, float* __restrict__ din, int n) {
    int i = blockIdx.x * blockDim.x + threadIdx.x;
    if (i < n) {
        atomicAdd(&dout[src[i]], 1.0f);
        atomicAdd(&din[dst[i]], 1.0f);
    }
}

__global__ void norm_kernel(float* __restrict__ p, int n) {
    int i = blockIdx.x * blockDim.x + threadIdx.x;
    if (i < n) {
        float v = p[i];
        p[i] = (v > 0.f) ? rsqrtf(v) : 0.f;
    }
}

// ---------------------------------------------------------------------------
// Edge scatter: agg[dst] += x[src] * ns[src]
// One warp per edge; each lane handles a float4 (HID=128 = 32 lanes * 4).
// Vector reduction (red.global.add.v4.f32, sm_90+) cuts atomic count 4x.
// ---------------------------------------------------------------------------
__global__ void scatter_kernel(const float* __restrict__ x,
                               const int* __restrict__ src,
                               const int* __restrict__ dst,
                               const float* __restrict__ ns,
                               float* __restrict__ agg, int n) {
    long long idx = (long long)blockIdx.x * blockDim.x + threadIdx.x;
    int e = (int)(idx >> 5);
    if (e >= n) return;
    int c = (int)(idx & 31);
    int s = src[e];
    int d = dst[e];
    float sc = __ldg(&ns[s]);
    float4 v = ((const float4*)(x + (size_t)s * HID))[c];
    float mx = v.x * sc, my = v.y * sc, mz = v.z * sc, mw = v.w * sc;
    float* p = agg + (size_t)d * HID + c * 4;
    asm volatile("red.global.add.v4.f32 [%0], {%1, %2, %3, %4};"
                 :: "l"(p), "f"(mx), "f"(my), "f"(mz), "f"(mw)
                 : "memory");
}

// ---------------------------------------------------------------------------
// Tiled SGEMM: C = epilogue( alpha * ((A .* rowscale) @ W + bias) )
// BM=128, BN=128, BK=16, 256 threads, 8x8 per-thread micro-tile.
// EPI_STORE:    C  = out
// EPI_ACC_RELU: C  = relu(C + out)
// EPI_ACC_RES:  C  = C + out + resid[row]
// ---------------------------------------------------------------------------
#define EPI_STORE 0
#define EPI_ACC_RELU 1
#define EPI_ACC_RES 2

template <int EPI, bool ROWSCALE>
__global__ __launch_bounds__(256)
void gemm_kernel(const float* __restrict__ A, const float* __restrict__ rs,
                 const float* __restrict__ W, const float* __restrict__ bias,
                 float alpha, float* __restrict__ C,
                 const float* __restrict__ resid,
                 int M, int N, int K) {
    __shared__ __align__(16) float As[16][132];
    __shared__ __align__(16) float Bs[16][128];

    const int tid = threadIdx.x;
    const int row0 = blockIdx.x * 128;
    const int col0 = blockIdx.y * 128;
    const int tx = tid & 15;   // 16 col-groups of 8
    const int ty = tid >> 4;   // 16 row-groups of 8

    float acc[8][8];
#pragma unroll
    for (int i = 0; i < 8; i++)
#pragma unroll
        for (int j = 0; j < 8; j++) acc[i][j] = 0.f;

    for (int k0 = 0; k0 < K; k0 += 16) {
        // ---- load A tile (128 x 16), transposed into As[k][m], rowscaled ----
#pragma unroll
        for (int it = 0; it < 2; it++) {
            int lin = tid + it * 256;      // 0..511
            int r = lin >> 2;              // 0..127
            int kc = (lin & 3) << 2;       // 0,4,8,12
            int grow = row0 + r;
            float4 v = make_float4(0.f, 0.f, 0.f, 0.f);
            if (grow < M) {
                v = *(const float4*)(A + (size_t)grow * K + (k0 + kc));
                if (ROWSCALE) {
                    float s = __ldg(&rs[grow]);
                    v.x *= s; v.y *= s; v.z *= s; v.w *= s;
                }
            }
            As[kc + 0][r] = v.x;
            As[kc + 1][r] = v.y;
            As[kc + 2][r] = v.z;
            As[kc + 3][r] = v.w;
        }
        // ---- load B tile (16 x 128) ----
#pragma unroll
        for (int it = 0; it < 2; it++) {
            int lin = tid + it * 256;
            int kk = lin >> 5;             // 0..15
            int nc = (lin & 31) << 2;      // 0..124
            *(float4*)&Bs[kk][nc] =
                *(const float4*)(W + (size_t)(k0 + kk) * N + col0 + nc);
        }
        __syncthreads();

#pragma unroll
        for (int kk = 0; kk < 16; kk++) {
            float4 a0 = *(const float4*)&As[kk][ty * 8];
            float4 a1 = *(const float4*)&As[kk][ty * 8 + 4];
            float4 b0 = *(const float4*)&Bs[kk][tx * 8];
            float4 b1 = *(const float4*)&Bs[kk][tx * 8 + 4];
            float a[8] = {a0.x, a0.y, a0.z, a0.w, a1.x, a1.y, a1.z, a1.w};
            float b[8] = {b0.x, b0.y, b0.z, b0.w, b1.x, b1.y, b1.z, b1.w};
#pragma unroll
            for (int i = 0; i < 8; i++)
#pragma unroll
                for (int j = 0; j < 8; j++)
                    acc[i][j] = fmaf(a[i], b[j], acc[i][j]);
        }
        __syncthreads();
    }

    // ---- epilogue ----
    float bv[8];
#pragma unroll
    for (int j = 0; j < 8; j++) bv[j] = bias[col0 + tx * 8 + j];

#pragma unroll
    for (int i = 0; i < 8; i++) {
        int row = row0 + ty * 8 + i;
        if (row < M) {
            float* cp = C + (size_t)row * N + col0 + tx * 8;
#pragma unroll
            for (int jj = 0; jj < 2; jj++) {
                float o0 = alpha * (acc[i][jj * 4 + 0] + bv[jj * 4 + 0]);
                float o1 = alpha * (acc[i][jj * 4 + 1] + bv[jj * 4 + 1]);
                float o2 = alpha * (acc[i][jj * 4 + 2] + bv[jj * 4 + 2]);
                float o3 = alpha * (acc[i][jj * 4 + 3] + bv[jj * 4 + 3]);
                if (EPI == EPI_STORE) {
                    *(float4*)(cp + jj * 4) = make_float4(o0, o1, o2, o3);
                } else {
                    float4 c = *(const float4*)(cp + jj * 4);
                    o0 += c.x; o1 += c.y; o2 += c.z; o3 += c.w;
                    if (EPI == EPI_ACC_RELU) {
                        o0 = fmaxf(o0, 0.f); o1 = fmaxf(o1, 0.f);
                        o2 = fmaxf(o2, 0.f); o3 = fmaxf(o3, 0.f);
                    }
                    if (EPI == EPI_ACC_RES) {
                        float4 r = *(const float4*)(resid + (size_t)row * N +
                                                    col0 + tx * 8 + jj * 4);
                        o0 += r.x; o1 += r.y; o2 += r.z; o3 += r.w;
                    }
                    *(float4*)(cp + jj * 4) = make_float4(o0, o1, o2, o3);
                }
            }
        }
    }
}

// ---------------------------------------------------------------------------
// Host launch
// ---------------------------------------------------------------------------
extern "C" void kernel_launch(void* const* d_in, const int* in_sizes, int n_in,
                              void* d_out, int out_size) {
    const float* frame = (const float*)d_in[0];
    const float* fe    = (const float*)d_in[1];
    const int* s_ff = (const int*)d_in[2];  const int* d_ff = (const int*)d_in[3];
    const int* s_fE = (const int*)d_in[4];  const int* d_fE = (const int*)d_in[5];  // frfe
    const int* s_ef = (const int*)d_in[6];  const int* d_ef = (const int*)d_in[7];  // fefr
    const int* s_ee = (const int*)d_in[8];  const int* d_ee = (const int*)d_in[9];
    const float* W_fr_lin = (const float*)d_in[10]; const float* b_fr_lin = (const float*)d_in[11];
    const float* W_fe_lin = (const float*)d_in[12]; const float* b_fe_lin = (const float*)d_in[13];
    const float* W_frfr = (const float*)d_in[14];   const float* b_frfr = (const float*)d_in[15];
    const float* W_frfe = (const float*)d_in[16];   const float* b_frfe = (const float*)d_in[17];
    const float* W_fefr = (const float*)d_in[18];   const float* b_fefr = (const float*)d_in[19];
    const float* W_fefe = (const float*)d_in[20];   const float* b_fefe = (const float*)d_in[21];
    const float* W_fr_fc = (const float*)d_in[22];  const float* b_fr_fc = (const float*)d_in[23];
    const float* W_fe_fc = (const float*)d_in[24];  const float* b_fe_fc = (const float*)d_in[25];

    float *x_fr, *x_fe, *h_fr, *h_fe, *aggFF, *aggEF, *aggFE, *aggEE, *deg;
    cudaGetSymbolAddress((void**)&x_fr, g_x_fr);
    cudaGetSymbolAddress((void**)&x_fe, g_x_fe);
    cudaGetSymbolAddress((void**)&h_fr, g_h_fr);
    cudaGetSymbolAddress((void**)&h_fe, g_h_fe);
    cudaGetSymbolAddress((void**)&aggFF, g_aggFF);
    cudaGetSymbolAddress((void**)&aggEF, g_aggEF);
    cudaGetSymbolAddress((void**)&aggFE, g_aggFE);
    cudaGetSymbolAddress((void**)&aggEE, g_aggEE);
    cudaGetSymbolAddress((void**)&deg, g_deg);

    // norm-vector layout inside g_deg
    float* ns_ff = deg;                       // frfr src (NF)
    float* nd_ff = deg + NF;                  // frfr dst (NF)
    float* ns_fE = deg + 2 * (size_t)NF;      // frfe src (NF)
    float* nd_ef = deg + 3 * (size_t)NF;      // fefr dst (NF)
    float* nd_fE = deg + 4 * (size_t)NF;                 // frfe dst (NE)
    float* ns_ef = deg + 4 * (size_t)NF + NE;            // fefr src (NE)
    float* ns_ee = deg + 4 * (size_t)NF + 2 * (size_t)NE;
    float* nd_ee = deg + 4 * (size_t)NF + 3 * (size_t)NE;

    float* out = (float*)d_out;
    float* o_frh = out;                                   // [NF, 512]
    float* o_feh = out + (size_t)NF * RAW;                // [NE, 512]
    float* o_hfr = o_feh + (size_t)NE * RAW;              // [NF, 128]
    float* o_hfe = o_hfr + (size_t)NF * HID;              // [NE, 128]

    const int T = 256;
    const size_t degN = (size_t)4 * NF + (size_t)4 * NE;  // 1.2M

    // ---- degrees & norms ----
    zero_kernel<<<(unsigned)((degN / 4 + T - 1) / T), T>>>(deg, degN / 4);
    int eb = (NEDGE + T - 1) / T;
    deg_kernel<<<eb, T>>>(s_ff, d_ff, ns_ff, nd_ff, NEDGE);
    deg_kernel<<<eb, T>>>(s_fE, d_fE, ns_fE, nd_fE, NEDGE);
    deg_kernel<<<eb, T>>>(s_ef, d_ef, ns_ef, nd_ef, NEDGE);
    deg_kernel<<<eb, T>>>(s_ee, d_ee, ns_ee, nd_ee, NEDGE);
    norm_kernel<<<(unsigned)((degN + T - 1) / T), T>>>(deg, (int)degN);

    // ---- input linears ----
    dim3 gF((NF + 127) / 128, 1);
    dim3 gE((NE + 127) / 128, 1);
    gemm_kernel<EPI_STORE, false><<<gF, T>>>(frame, nullptr, W_fr_lin, b_fr_lin,
                                             1.f, x_fr, nullptr, NF, HID, RAW);
    gemm_kernel<EPI_STORE, false><<<gE, T>>>(fe, nullptr, W_fe_lin, b_fe_lin,
                                             1.f, x_fe, nullptr, NE, HID, RAW);

    const size_t aF4 = (size_t)NF * HID / 4;
    const size_t aE4 = (size_t)NE * HID / 4;
    const unsigned zF = (unsigned)((aF4 + T - 1) / T);
    const unsigned zE = (unsigned)((aE4 + T - 1) / T);
    long long sc_tot = (long long)NEDGE * 32;
    int sb = (int)((sc_tot + T - 1) / T);

    // ---- layer 1 ----
    zero_kernel<<<zF, T>>>(aggFF, aF4);
    zero_kernel<<<zF, T>>>(aggEF, aF4);
    zero_kernel<<<zE, T>>>(aggFE, aE4);
    zero_kernel<<<zE, T>>>(aggEE, aE4);
    scatter_kernel<<<sb, T>>>(x_fr, s_ff, d_ff, ns_ff, aggFF, NEDGE);
    scatter_kernel<<<sb, T>>>(x_fr, s_fE, d_fE, ns_fE, aggFE, NEDGE);
    scatter_kernel<<<sb, T>>>(x_fe, s_ef, d_ef, ns_ef, aggEF, NEDGE);
    scatter_kernel<<<sb, T>>>(x_fe, s_ee, d_ee, ns_ee, aggEE, NEDGE);
    gemm_kernel<EPI_STORE, true><<<gF, T>>>(aggFF, nd_ff, W_frfr, b_frfr,
                                            0.5f, h_fr, nullptr, NF, HID, HID);
    gemm_kernel<EPI_ACC_RELU, true><<<gF, T>>>(aggEF, nd_ef, W_fefr, b_fefr,
                                               0.5f, h_fr, nullptr, NF, HID, HID);
    gemm_kernel<EPI_STORE, true><<<gE, T>>>(aggFE, nd_fE, W_frfe, b_frfe,
                                            0.5f, h_fe, nullptr, NE, HID, HID);
    gemm_kernel<EPI_ACC_RELU, true><<<gE, T>>>(aggEE, nd_ee, W_fefe, b_fefe,
                                               0.5f, h_fe, nullptr, NE, HID, HID);

    // ---- layer 2 (writes h directly into output region, residual = x) ----
    zero_kernel<<<zF, T>>>(aggFF, aF4);
    zero_kernel<<<zF, T>>>(aggEF, aF4);
    zero_kernel<<<zE, T>>>(aggFE, aE4);
    zero_kernel<<<zE, T>>>(aggEE, aE4);
    scatter_kernel<<<sb, T>>>(h_fr, s_ff, d_ff, ns_ff, aggFF, NEDGE);
    scatter_kernel<<<sb, T>>>(h_fr, s_fE, d_fE, ns_fE, aggFE, NEDGE);
    scatter_kernel<<<sb, T>>>(h_fe, s_ef, d_ef, ns_ef, aggEF, NEDGE);
    scatter_kernel<<<sb, T>>>(h_fe, s_ee, d_ee, ns_ee, aggEE, NEDGE);
    gemm_kernel<EPI_STORE, true><<<gF, T>>>(aggFF, nd_ff, W_frfr, b_frfr,
                                            0.5f, o_hfr, nullptr, NF, HID, HID);
    gemm_kernel<EPI_ACC_RES, true><<<gF, T>>>(aggEF, nd_ef, W_fefr, b_fefr,
                                              0.5f, o_hfr, x_fr, NF, HID, HID);
    gemm_kernel<EPI_STORE, true><<<gE, T>>>(aggFE, nd_fE, W_frfe, b_frfe,
                                            0.5f, o_hfe, nullptr, NE, HID, HID);
    gemm_kernel<EPI_ACC_RES, true><<<gE, T>>>(aggEE, nd_ee, W_fefe, b_fefe,
                                              0.5f, o_hfe, x_fe, NE, HID, HID);

    // ---- output FCs ----
    dim3 gFo((NF + 127) / 128, RAW / 128);
    dim3 gEo((NE + 127) / 128, RAW / 128);
    gemm_kernel<EPI_STORE, false><<<gFo, T>>>(o_hfr, nullptr, W_fr_fc, b_fr_fc,
                                              1.f, o_frh, nullptr, NF, RAW, HID);
    gemm_kernel<EPI_STORE, false><<<gEo, T>>>(o_hfe, nullptr, W_fe_fc, b_fe_fc,
                                              1.f, o_feh, nullptr, NE, RAW, HID);
}

// round 3
// speedup vs baseline: 1.7778x; 1.7778x over previous
#include <cuda_runtime.h>
#include <cstdint>
#include <cstddef>

// ---------------------------------------------------------------------------
// Problem constants
// ---------------------------------------------------------------------------
#define NF 100000
#define NE 200000
#define HID 128
#define RAW 512
#define NEDGE 1000000

// ---------------------------------------------------------------------------
// Scratch (device globals -- no allocation allowed)
// ---------------------------------------------------------------------------
__device__ float g_x_fr[(size_t)NF * HID];
__device__ float g_x_fe[(size_t)NE * HID];
__device__ float g_h_fr[(size_t)NF * HID];
__device__ float g_h_fe[(size_t)NE * HID];
__device__ float g_aggF[(size_t)NF * 256];   // [FF | EF] per fr-dst row
__device__ float g_aggE[(size_t)NE * 256];   // [FE | EE] per fe-dst row
__device__ float g_deg[(size_t)4 * NF + (size_t)4 * NE];
__device__ float g_WcatF[(size_t)256 * HID]; // [256][128]: rows 0-127 W_frfr, 128-255 W_fefr
__device__ float g_WcatE[(size_t)256 * HID];
__device__ float g_bias_gF[HID];
__device__ float g_bias_gE[HID];

// ---------------------------------------------------------------------------
// Helpers
// ---------------------------------------------------------------------------
__device__ __forceinline__ uint32_t smem_u32(const void* p) {
    uint32_t r;
    asm("{ .reg .u64 t; cvta.to.shared.u64 t, %1; cvt.u32.u64 %0, t; }"
        : "=r"(r) : "l"(p));
    return r;
}

__device__ __forceinline__ uint32_t f2tf32(float f) {
    uint32_t u;
    asm("cvt.rna.tf32.f32 %0, %1;" : "=r"(u) : "f"(f));
    return u;
}

// ---------------------------------------------------------------------------
// Utility kernels
// ---------------------------------------------------------------------------
__global__ void zero_kernel(float* __restrict__ p, size_t n4) {
    size_t i = (size_t)blockIdx.x * blockDim.x + threadIdx.x;
    if (i < n4) ((float4*)p)[i] = make_float4(0.f, 0.f, 0.f, 0.f);
}

__global__ void deg_kernel(const int* __restrict__ src, const int* __restrict__ dst,
                           float* __restrict__ dout, float* __restrict__ din, int n) {
    int i = blockIdx.x * blockDim.x + threadIdx.x;
    if (i < n) {
        atomicAdd(&dout[src[i]], 1.0f);
        atomicAdd(&din[dst[i]], 1.0f);
    }
}

__global__ void norm_kernel(float* __restrict__ p, int n) {
    int i = blockIdx.x * blockDim.x + threadIdx.x;
    if (i < n) {
        float v = p[i];
        p[i] = (v > 0.f) ? rsqrtf(v) : 0.f;
    }
}

// Wcat[k][n]: k<128 -> W1[k][n], else W2[k-128][n].  (both [128][128] row-major)
__global__ void concat_kernel(const float* __restrict__ W1, const float* __restrict__ W2,
                              float* __restrict__ out) {
    int idx = blockIdx.x * blockDim.x + threadIdx.x;
    if (idx < 256 * 128) {
        int k = idx >> 7, n = idx & 127;
        out[idx] = (k < 128) ? W1[(size_t)k * 128 + n] : W2[(size_t)(k - 128) * 128 + n];
    }
}

__global__ void bias_combine_kernel(const float* __restrict__ b1,
                                    const float* __restrict__ b2,
                                    float* __restrict__ out, float alpha) {
    int i = blockIdx.x * blockDim.x + threadIdx.x;
    if (i < HID) out[i] = alpha * (b1[i] + b2[i]);
}

// ---------------------------------------------------------------------------
// Edge scatter: agg[dst*256 + off] += x[src] * ns[src] * nd[dst]
// One warp per edge, float4 per lane, vector reduction.
// ---------------------------------------------------------------------------
__global__ void scatter_kernel(const float* __restrict__ x,
                               const int* __restrict__ src,
                               const int* __restrict__ dst,
                               const float* __restrict__ ns,
                               const float* __restrict__ nd,
                               float* __restrict__ agg, int rel_off, int n) {
    long long idx = (long long)blockIdx.x * blockDim.x + threadIdx.x;
    int e = (int)(idx >> 5);
    if (e >= n) return;
    int c = (int)(idx & 31);
    int s = src[e];
    int d = dst[e];
    float sc = __ldg(&ns[s]) * __ldg(&nd[d]);
    float4 v = ((const float4*)(x + (size_t)s * HID))[c];
    float mx = v.x * sc, my = v.y * sc, mz = v.z * sc, mw = v.w * sc;
    float* p = agg + (size_t)d * 256 + rel_off + c * 4;
    asm volatile("red.global.add.v4.f32 [%0], {%1, %2, %3, %4};"
                 :: "l"(p), "f"(mx), "f"(my), "f"(mz), "f"(mw)
                 : "memory");
}

// ---------------------------------------------------------------------------
// TF32 mma.sync GEMM:  C = epi( alpha * (A @ B) + bias )
//   A: [M][K] fp32 row-major      B: [K][ldB] fp32 row-major (native weights)
// Tile 128x128, BK=16, 8 warps (each 32x64), cp.async double buffer.
// EPI: 0 = store, 1 = relu, 2 = +resid (resid has same ldC row stride)
// ---------------------------------------------------------------------------
template <int EPI>
__global__ void __launch_bounds__(256, 2)
mma_gemm(const float* __restrict__ A, const float* __restrict__ B,
         const float* __restrict__ bias, const float* __restrict__ resid,
         float* __restrict__ C, int M, int K, int ldB, int ldC, float alpha) {
    __shared__ float As[2][128][20];   // rows: m, cols: k (pad 20 -> conflict-free frags)
    __shared__ float Bs[2][16][136];   // rows: k, cols: n (pad 136 -> conflict-free frags)

    const int tid = threadIdx.x;
    const int wid = tid >> 5;
    const int lane = tid & 31;
    const int g = lane >> 2;         // group id 0..7
    const int tig = lane & 3;        // thread-in-group 0..3
    const int warp_m = (wid & 3) * 32;
    const int warp_n = (wid >> 2) * 64;
    const int row0 = blockIdx.x * 128;
    const int n0 = blockIdx.y * 128;

    float c[2][8][4];
#pragma unroll
    for (int mt = 0; mt < 2; mt++)
#pragma unroll
        for (int nt = 0; nt < 8; nt++)
#pragma unroll
            for (int q = 0; q < 4; q++) c[mt][nt][q] = 0.f;

    const int NIT = K >> 4;

    auto load_stage = [&](int s, int k0) {
        // A: 128 rows x 16 k (4 x 16B chunks per row) = 512 chunks
#pragma unroll
        for (int i = 0; i < 2; i++) {
            int cid = tid + i * 256;
            int m = cid >> 2, kc = (cid & 3) << 2;
            const float* src = A + (size_t)(row0 + m) * K + k0 + kc;
            uint32_t dst = smem_u32(&As[s][m][kc]);
            unsigned sz = (row0 + m < M) ? 16u : 0u;
            asm volatile("cp.async.cg.shared.global [%0], [%1], 16, %2;"
                         :: "r"(dst), "l"(src), "r"(sz));
        }
        // B: 16 rows x 128 n (32 chunks per row) = 512 chunks
#pragma unroll
        for (int i = 0; i < 2; i++) {
            int cid = tid + i * 256;
            int k = cid >> 5, nch = (cid & 31) << 2;
            const float* src = B + (size_t)(k0 + k) * ldB + n0 + nch;
            uint32_t dst = smem_u32(&Bs[s][k][nch]);
            asm volatile("cp.async.cg.shared.global [%0], [%1], 16;"
                         :: "r"(dst), "l"(src));
        }
        asm volatile("cp.async.commit_group;");
    };

    load_stage(0, 0);

    for (int it = 0; it < NIT; it++) {
        int s = it & 1;
        if (it + 1 < NIT) {
            load_stage(s ^ 1, (it + 1) << 4);
            asm volatile("cp.async.wait_group 1;");
        } else {
            asm volatile("cp.async.wait_group 0;");
        }
        __syncthreads();

#pragma unroll
        for (int ks = 0; ks < 2; ks++) {
            const int kb = ks << 3;
            uint32_t a[2][4];
#pragma unroll
            for (int mt = 0; mt < 2; mt++) {
                int mr = warp_m + mt * 16 + g;
                a[mt][0] = f2tf32(As[s][mr][kb + tig]);
                a[mt][1] = f2tf32(As[s][mr + 8][kb + tig]);
                a[mt][2] = f2tf32(As[s][mr][kb + tig + 4]);
                a[mt][3] = f2tf32(As[s][mr + 8][kb + tig + 4]);
            }
            uint32_t b[8][2];
#pragma unroll
            for (int nt = 0; nt < 8; nt++) {
                int nc = warp_n + nt * 8 + g;
                b[nt][0] = f2tf32(Bs[s][kb + tig][nc]);
                b[nt][1] = f2tf32(Bs[s][kb + tig + 4][nc]);
            }
#pragma unroll
            for (int mt = 0; mt < 2; mt++)
#pragma unroll
                for (int nt = 0; nt < 8; nt++) {
                    asm volatile(
                        "mma.sync.aligned.m16n8k8.row.col.f32.tf32.tf32.f32 "
                        "{%0,%1,%2,%3}, {%4,%5,%6,%7}, {%8,%9}, {%0,%1,%2,%3};"
                        : "+f"(c[mt][nt][0]), "+f"(c[mt][nt][1]),
                          "+f"(c[mt][nt][2]), "+f"(c[mt][nt][3])
                        : "r"(a[mt][0]), "r"(a[mt][1]), "r"(a[mt][2]), "r"(a[mt][3]),
                          "r"(b[nt][0]), "r"(b[nt][1]));
                }
        }
        __syncthreads();
    }

    // ---- epilogue: direct register -> gmem ----
#pragma unroll
    for (int nt = 0; nt < 8; nt++) {
        int col = n0 + warp_n + nt * 8 + tig * 2;
        float b0 = bias[col], b1 = bias[col + 1];
#pragma unroll
        for (int mt = 0; mt < 2; mt++) {
#pragma unroll
            for (int h = 0; h < 2; h++) {
                int row = row0 + warp_m + mt * 16 + g + h * 8;
                if (row < M) {
                    float o0 = alpha * c[mt][nt][h * 2 + 0] + b0;
                    float o1 = alpha * c[mt][nt][h * 2 + 1] + b1;
                    if (EPI == 1) { o0 = fmaxf(o0, 0.f); o1 = fmaxf(o1, 0.f); }
                    if (EPI == 2) {
                        const float* rp = resid + (size_t)row * ldC + col;
                        o0 += rp[0]; o1 += rp[1];
                    }
                    *(float2*)(C + (size_t)row * ldC + col) = make_float2(o0, o1);
                }
            }
        }
    }
}

// ---------------------------------------------------------------------------
// Host launch
// ---------------------------------------------------------------------------
extern "C" void kernel_launch(void* const* d_in, const int* in_sizes, int n_in,
                              void* d_out, int out_size) {
    const float* frame = (const float*)d_in[0];
    const float* fe    = (const float*)d_in[1];
    const int* s_ff = (const int*)d_in[2];  const int* d_ff = (const int*)d_in[3];
    const int* s_fE = (const int*)d_in[4];  const int* d_fE = (const int*)d_in[5];  // frfe
    const int* s_ef = (const int*)d_in[6];  const int* d_ef = (const int*)d_in[7];  // fefr
    const int* s_ee = (const int*)d_in[8];  const int* d_ee = (const int*)d_in[9];
    const float* W_fr_lin = (const float*)d_in[10]; const float* b_fr_lin = (const float*)d_in[11];
    const float* W_fe_lin = (const float*)d_in[12]; const float* b_fe_lin = (const float*)d_in[13];
    const float* W_frfr = (const float*)d_in[14];   const float* b_frfr = (const float*)d_in[15];
    const float* W_frfe = (const float*)d_in[16];   const float* b_frfe = (const float*)d_in[17];
    const float* W_fefr = (const float*)d_in[18];   const float* b_fefr = (const float*)d_in[19];
    const float* W_fefe = (const float*)d_in[20];   const float* b_fefe = (const float*)d_in[21];
    const float* W_fr_fc = (const float*)d_in[22];  const float* b_fr_fc = (const float*)d_in[23];
    const float* W_fe_fc = (const float*)d_in[24];  const float* b_fe_fc = (const float*)d_in[25];

    float *x_fr, *x_fe, *h_fr, *h_fe, *aggF, *aggE, *deg;
    float *WcatF, *WcatE, *bias_gF, *bias_gE;
    cudaGetSymbolAddress((void**)&x_fr, g_x_fr);
    cudaGetSymbolAddress((void**)&x_fe, g_x_fe);
    cudaGetSymbolAddress((void**)&h_fr, g_h_fr);
    cudaGetSymbolAddress((void**)&h_fe, g_h_fe);
    cudaGetSymbolAddress((void**)&aggF, g_aggF);
    cudaGetSymbolAddress((void**)&aggE, g_aggE);
    cudaGetSymbolAddress((void**)&deg, g_deg);
    cudaGetSymbolAddress((void**)&WcatF, g_WcatF);
    cudaGetSymbolAddress((void**)&WcatE, g_WcatE);
    cudaGetSymbolAddress((void**)&bias_gF, g_bias_gF);
    cudaGetSymbolAddress((void**)&bias_gE, g_bias_gE);

    // norm-vector layout inside g_deg
    float* ns_ff = deg;
    float* nd_ff = deg + NF;
    float* ns_fE = deg + 2 * (size_t)NF;
    float* nd_ef = deg + 3 * (size_t)NF;
    float* nd_fE = deg + 4 * (size_t)NF;
    float* ns_ef = deg + 4 * (size_t)NF + NE;
    float* ns_ee = deg + 4 * (size_t)NF + 2 * (size_t)NE;
    float* nd_ee = deg + 4 * (size_t)NF + 3 * (size_t)NE;

    float* out = (float*)d_out;
    float* o_frh = out;
    float* o_feh = out + (size_t)NF * RAW;
    float* o_hfr = o_feh + (size_t)NE * RAW;
    float* o_hfe = o_hfr + (size_t)NF * HID;

    const int T = 256;

    // ---- weight prep ----
    concat_kernel<<<(256 * 128 + T - 1) / T, T>>>(W_frfr, W_fefr, WcatF);
    concat_kernel<<<(256 * 128 + T - 1) / T, T>>>(W_frfe, W_fefe, WcatE);
    bias_combine_kernel<<<1, 128>>>(b_frfr, b_fefr, bias_gF, 0.5f);
    bias_combine_kernel<<<1, 128>>>(b_frfe, b_fefe, bias_gE, 0.5f);

    // ---- degrees & norms ----
    const size_t degN = (size_t)4 * NF + (size_t)4 * NE;
    zero_kernel<<<(unsigned)((degN / 4 + T - 1) / T), T>>>(deg, degN / 4);
    int eb = (NEDGE + T - 1) / T;
    deg_kernel<<<eb, T>>>(s_ff, d_ff, ns_ff, nd_ff, NEDGE);
    deg_kernel<<<eb, T>>>(s_fE, d_fE, ns_fE, nd_fE, NEDGE);
    deg_kernel<<<eb, T>>>(s_ef, d_ef, ns_ef, nd_ef, NEDGE);
    deg_kernel<<<eb, T>>>(s_ee, d_ee, ns_ee, nd_ee, NEDGE);
    norm_kernel<<<(unsigned)((degN + T - 1) / T), T>>>(deg, (int)degN);

    const unsigned gFx = (NF + 127) / 128;   // 782
    const unsigned gEx = (NE + 127) / 128;   // 1563

    // ---- input linears (K=512, N=128) ----
    mma_gemm<0><<<dim3(gFx, 1), 256>>>(frame, W_fr_lin, b_fr_lin, nullptr,
                                       x_fr, NF, RAW, HID, HID, 1.f);
    mma_gemm<0><<<dim3(gEx, 1), 256>>>(fe, W_fe_lin, b_fe_lin, nullptr,
                                       x_fe, NE, RAW, HID, HID, 1.f);

    const size_t aF4 = (size_t)NF * 256 / 4;
    const size_t aE4 = (size_t)NE * 256 / 4;
    const unsigned zF = (unsigned)((aF4 + T - 1) / T);
    const unsigned zE = (unsigned)((aE4 + T - 1) / T);
    long long sc_tot = (long long)NEDGE * 32;
    int sb = (int)((sc_tot + T - 1) / T);

    // ---- layer 1 ----
    zero_kernel<<<zF, T>>>(aggF, aF4);
    zero_kernel<<<zE, T>>>(aggE, aE4);
    scatter_kernel<<<sb, T>>>(x_fr, s_ff, d_ff, ns_ff, nd_ff, aggF, 0, NEDGE);
    scatter_kernel<<<sb, T>>>(x_fe, s_ef, d_ef, ns_ef, nd_ef, aggF, 128, NEDGE);
    scatter_kernel<<<sb, T>>>(x_fr, s_fE, d_fE, ns_fE, nd_fE, aggE, 0, NEDGE);
    scatter_kernel<<<sb, T>>>(x_fe, s_ee, d_ee, ns_ee, nd_ee, aggE, 128, NEDGE);
    mma_gemm<1><<<dim3(gFx, 1), 256>>>(aggF, WcatF, bias_gF, nullptr,
                                       h_fr, NF, 256, HID, HID, 0.5f);
    mma_gemm<1><<<dim3(gEx, 1), 256>>>(aggE, WcatE, bias_gE, nullptr,
                                       h_fe, NE, 256, HID, HID, 0.5f);

    // ---- layer 2 (writes h into output region, residual = x) ----
    zero_kernel<<<zF, T>>>(aggF, aF4);
    zero_kernel<<<zE, T>>>(aggE, aE4);
    scatter_kernel<<<sb, T>>>(h_fr, s_ff, d_ff, ns_ff, nd_ff, aggF, 0, NEDGE);
    scatter_kernel<<<sb, T>>>(h_fe, s_ef, d_ef, ns_ef, nd_ef, aggF, 128, NEDGE);
    scatter_kernel<<<sb, T>>>(h_fr, s_fE, d_fE, ns_fE, nd_fE, aggE, 0, NEDGE);
    scatter_kernel<<<sb, T>>>(h_fe, s_ee, d_ee, ns_ee, nd_ee, aggE, 128, NEDGE);
    mma_gemm<2><<<dim3(gFx, 1), 256>>>(aggF, WcatF, bias_gF, x_fr,
                                       o_hfr, NF, 256, HID, HID, 0.5f);
    mma_gemm<2><<<dim3(gEx, 1), 256>>>(aggE, WcatE, bias_gE, x_fe,
                                       o_hfe, NE, 256, HID, HID, 0.5f);

    // ---- output FCs (K=128, N=512) ----
    mma_gemm<0><<<dim3(gFx, 4), 256>>>(o_hfr, W_fr_fc, b_fr_fc, nullptr,
                                       o_frh, NF, HID, RAW, RAW, 1.f);
    mma_gemm<0><<<dim3(gEx, 4), 256>>>(o_hfe, W_fe_fc, b_fe_fc, nullptr,
                                       o_feh, NE, HID, RAW, RAW, 1.f);
}